// round 2
// baseline (speedup 1.0000x reference)
#include <cuda_runtime.h>

#define BB 32
#define SS 512
#define LL 64
#define TSTART 61
#define TSTOP 62

// Grid: 64 blocks x 64 threads.
//  blocks [0,32): forward (unlabeled) score for batch b, prob-domain scan.
//  blocks [32,64): labeled path score for batch b-32.
__global__ __launch_bounds__(64, 1)
void crf_kernel(const float* __restrict__ enc,     // [B,S,L]
                const float* __restrict__ trans,   // [L,L]
                const int*   __restrict__ lens,    // [B]
                const int*   __restrict__ tags,    // [B,S]
                float*       __restrict__ out)     // [2*B]
{
    __shared__ float  sE[LL * LL];
    __shared__ float4 spbuf[2][LL / 4];
    __shared__ float  sred[2];
    const int j = threadIdx.x;

    if (blockIdx.x < BB) {
        const int b = blockIdx.x;

        // Build E = exp(T) in shared (coalesced), then pull column j into regs.
        #pragma unroll
        for (int r = 0; r < LL; r++)
            sE[r * LL + j] = __expf(trans[r * LL + j]);
        __syncthreads();
        float Ecol[LL];
        #pragma unroll
        for (int i = 0; i < LL; i++) Ecol[i] = sE[i * LL + j];
        const float eStop = __expf(trans[j * LL + TSTOP]);

        const int len = lens[b];
        const float* encb = enc + (size_t)b * SS * LL;

        // p_0[j] = exp(T[START,j] + enc[b,0,j]);  alpha = C + log(p)
        float p = __expf(trans[TSTART * LL + j] + encb[j]);
        float C = 0.0f;

        float enc_next = encb[(len > 1 ? LL : 0) + j];

        for (int t = 1; t < len; ++t) {
            float* sp = (float*)spbuf[t & 1];
            sp[j] = p;
            const float e_cur = enc_next;
            const int tn = (t + 1 < len) ? (t + 1) : t;   // clamped prefetch
            enc_next = encb[tn * LL + j];
            __syncthreads();

            const float4* sp4 = spbuf[t & 1];
            float a0 = 0.f, a1 = 0.f, a2 = 0.f, a3 = 0.f;
            #pragma unroll
            for (int i = 0; i < LL / 4; i++) {
                const float4 v = sp4[i];
                a0 = fmaf(v.x, Ecol[4 * i + 0], a0);
                a1 = fmaf(v.y, Ecol[4 * i + 1], a1);
                a2 = fmaf(v.z, Ecol[4 * i + 2], a2);
                a3 = fmaf(v.w, Ecol[4 * i + 3], a3);
            }
            const float dot = (a0 + a1) + (a2 + a3);
            const float f = __expf(e_cur);

            if ((t & 3) == 0) {
                // Uniform renorm: max over shared p_{t-1} (identical on all threads).
                float m = 0.f;
                #pragma unroll
                for (int i = 0; i < LL / 4; i++) {
                    const float4 v = sp4[i];
                    m = fmaxf(m, fmaxf(fmaxf(v.x, v.y), fmaxf(v.z, v.w)));
                }
                C += __logf(m);
                p = dot * f * (1.0f / m);
            } else {
                p = dot * f;
            }
        }

        // unlabeled = C + log( sum_j p[j] * exp(T[j,STOP]) )
        float v = p * eStop;
        #pragma unroll
        for (int off = 16; off; off >>= 1)
            v += __shfl_xor_sync(0xffffffffu, v, off);
        if ((j & 31) == 0) sred[j >> 5] = v;
        __syncthreads();
        if (j == 0) out[b] = C + __logf(sred[0] + sred[1]);
    } else {
        // ---- labeled path score ----
        const int b = blockIdx.x - BB;
        const int len = lens[b];
        const float* encb = enc + (size_t)b * SS * LL;
        const int* tg = tags + b * SS;

        float acc = 0.f;
        for (int t = 1 + j; t < len; t += LL) {
            const int tt = tg[t];
            const int tp = tg[t - 1];
            acc += trans[tp * LL + tt] + encb[t * LL + tt];
        }
        #pragma unroll
        for (int off = 16; off; off >>= 1)
            acc += __shfl_xor_sync(0xffffffffu, acc, off);
        if ((j & 31) == 0) sred[j >> 5] = acc;
        __syncthreads();
        if (j == 0) {
            const int t0 = tg[0];
            const float begin = trans[TSTART * LL + t0] + encb[t0];
            const float endsc = trans[tg[len - 1] * LL + TSTOP];
            out[BB + b] = sred[0] + sred[1] + begin + endsc;
        }
    }
}

extern "C" void kernel_launch(void* const* d_in, const int* in_sizes, int n_in,
                              void* d_out, int out_size) {
    const float* enc   = (const float*)d_in[0];   // encoder_scores [32,512,64]
    const float* trans = (const float*)d_in[1];   // transition [64,64]
    const int*   lens  = (const int*)d_in[2];     // word_seq_lens [32]
    const int*   tags  = (const int*)d_in[3];     // tags [32,512]
    // d_in[4] = mask: unused (recomputed from lens)
    float* out = (float*)d_out;                   // [64] = unlabeled(32) ++ labeled(32)
    (void)in_sizes; (void)n_in; (void)out_size;

    crf_kernel<<<2 * BB, LL>>>(enc, trans, lens, tags, out);
}

// round 3
// speedup vs baseline: 1.2324x; 1.2324x over previous
#include <cuda_runtime.h>

#define BB 32
#define SS 512
#define LL 64
#define TSTART 61
#define TSTOP 62

// Forward blocks: 128 threads. thread t: j = t>>1 (output state), s = t&1 (half of i-range).
// Each thread holds E[i][j] for i in [32s, 32s+32).
template<bool REN>
__device__ __forceinline__ void crf_step(float& p, float& C, float f,
                                         float* spb, const float* E, int j, int s) {
    if (s == 0) spb[j] = p;          // publish p_{t-1}
    __syncthreads();
    const float4* sp4 = (const float4*)spb + 8 * s;
    float b[8], m = 0.f;
    #pragma unroll
    for (int k = 0; k < 8; k++) {
        const float4 v = sp4[k];
        b[k] = fmaf(v.x, E[4*k+0], fmaf(v.y, E[4*k+1], fmaf(v.z, E[4*k+2], v.w * E[4*k+3])));
        if (REN) m = fmaxf(m, fmaxf(fmaxf(v.x, v.y), fmaxf(v.z, v.w)));
    }
    float dot = ((b[0]+b[1]) + (b[2]+b[3])) + ((b[4]+b[5]) + (b[6]+b[7]));
    dot += __shfl_xor_sync(0xffffffffu, dot, 1);   // combine lane pair -> full 64-term dot
    if (REN) {
        m = fmaxf(m, __shfl_xor_sync(0xffffffffu, m, 1));  // max over all 64 (uniform)
        C += __logf(m);
        p = dot * f * __fdividef(1.0f, m);
    } else {
        p = dot * f;
    }
}

__global__ __launch_bounds__(128, 1)
void crf_kernel(const float* __restrict__ enc,     // [B,S,L]
                const float* __restrict__ trans,   // [L,L]
                const int*   __restrict__ lens,    // [B]
                const int*   __restrict__ tags,    // [B,S]
                float*       __restrict__ out)     // [2*B]
{
    __shared__ float spbuf[2][LL];
    __shared__ float sred[4];
    const int tid = threadIdx.x;

    if (blockIdx.x < BB) {
        const int b = blockIdx.x;
        const int j = tid >> 1;
        const int s = tid & 1;

        // E column halves in registers: E[i][j], i in [32s, 32s+32)
        float E[32];
        #pragma unroll
        for (int i = 0; i < 32; i++)
            E[i] = __expf(trans[(32 * s + i) * LL + j]);
        const float eStop = __expf(trans[j * LL + TSTOP]);

        const int len = lens[b];
        const float* encb = enc + (size_t)b * SS * LL;

        float p = __expf(trans[TSTART * LL + j] + encb[j]);   // p_0
        float C = 0.0f;

        // software-pipelined f = exp(enc) for steps t..t+3
        float fq[4];
        #pragma unroll
        for (int k = 0; k < 4; k++) {
            const int tt = min(1 + k, len - 1);
            fq[k] = __expf(encb[tt * LL + j]);
        }

        int t = 1;
        for (; t + 3 < len; t += 4) {
            float er[4];
            #pragma unroll
            for (int k = 0; k < 4; k++) {
                const int tt = min(t + 4 + k, len - 1);
                er[k] = encb[tt * LL + j];          // issue early, consume next group
            }
            // t = 1 mod 4: parities 1,0,1,0; renorm at t+3 == 0 mod 4
            crf_step<false>(p, C, fq[0], spbuf[1], E, j, s);
            crf_step<false>(p, C, fq[1], spbuf[0], E, j, s);
            crf_step<false>(p, C, fq[2], spbuf[1], E, j, s);
            crf_step<true >(p, C, fq[3], spbuf[0], E, j, s);
            #pragma unroll
            for (int k = 0; k < 4; k++) fq[k] = __expf(er[k]);
        }
        // tail (<= 3 steps); fq[k] holds exp(enc[t+k]) by loop invariant
        #pragma unroll
        for (int k = 0; k < 3; k++) {
            if (t + k < len) {
                if (((t + k) & 3) == 0)
                    crf_step<true >(p, C, fq[k], spbuf[(t + k) & 1], E, j, s);
                else
                    crf_step<false>(p, C, fq[k], spbuf[(t + k) & 1], E, j, s);
            }
        }

        // unlabeled = C + log( sum_j p[j] * exp(T[j,STOP]) )
        float v = (s == 0) ? p * eStop : 0.0f;
        #pragma unroll
        for (int off = 16; off; off >>= 1)
            v += __shfl_xor_sync(0xffffffffu, v, off);
        if ((tid & 31) == 0) sred[tid >> 5] = v;
        __syncthreads();
        if (tid == 0)
            out[b] = C + __logf(((sred[0] + sred[1]) + (sred[2] + sred[3])));
    } else {
        // ---- labeled path score ----
        const int b = blockIdx.x - BB;
        const int len = lens[b];
        const float* encb = enc + (size_t)b * SS * LL;
        const int* tg = tags + b * SS;

        float acc = 0.f;
        for (int t = 1 + tid; t < len; t += 128) {
            const int tt = tg[t];
            const int tp = tg[t - 1];
            acc += trans[tp * LL + tt] + encb[t * LL + tt];
        }
        #pragma unroll
        for (int off = 16; off; off >>= 1)
            acc += __shfl_xor_sync(0xffffffffu, acc, off);
        if ((tid & 31) == 0) sred[tid >> 5] = acc;
        __syncthreads();
        if (tid == 0) {
            const int t0 = tg[0];
            const float begin = trans[TSTART * LL + t0] + encb[t0];
            const float endsc = trans[tg[len - 1] * LL + TSTOP];
            out[BB + b] = ((sred[0] + sred[1]) + (sred[2] + sred[3])) + begin + endsc;
        }
    }
}

extern "C" void kernel_launch(void* const* d_in, const int* in_sizes, int n_in,
                              void* d_out, int out_size) {
    const float* enc   = (const float*)d_in[0];   // encoder_scores [32,512,64]
    const float* trans = (const float*)d_in[1];   // transition [64,64]
    const int*   lens  = (const int*)d_in[2];     // word_seq_lens [32]
    const int*   tags  = (const int*)d_in[3];     // tags [32,512]
    // d_in[4] = mask: unused (recomputed from lens)
    float* out = (float*)d_out;                   // [64] = unlabeled(32) ++ labeled(32)
    (void)in_sizes; (void)n_in; (void)out_size;

    crf_kernel<<<2 * BB, 128>>>(enc, trans, lens, tags, out);
}

// round 4
// speedup vs baseline: 1.5213x; 1.2344x over previous
#include <cuda_runtime.h>

#define BB 32
#define SS 512
#define LL 64
#define TSTART 61
#define TSTOP 62

__device__ __forceinline__ void barx(int id) {
    asm volatile("bar.sync %0, 128;" :: "r"(id) : "memory");
}

// One scan step for a 128-thread half. Thread (x = lt>>1, s = lt&1) owns output
// state x and the i-range [32s,32s+32) of the 64-term dot (weights in W[32]).
// u is the published vector value for state x (identical in both s lanes).
template<bool REN>
__device__ __forceinline__ float stepf(float u, float g, float* spb, const float* W,
                                       int x, int s, int barid, float& C) {
    if (s == 0) spb[x] = u;
    barx(barid);
    const float4* sp4 = (const float4*)spb + 8 * s;
    float b[8], mm = 0.f;
    #pragma unroll
    for (int k = 0; k < 8; k++) {
        const float4 v = sp4[k];
        b[k] = fmaf(v.x, W[4*k+0], fmaf(v.y, W[4*k+1], fmaf(v.z, W[4*k+2], v.w * W[4*k+3])));
        if (REN) mm = fmaxf(mm, fmaxf(fmaxf(v.x, v.y), fmaxf(v.z, v.w)));
    }
    float dot = ((b[0]+b[1]) + (b[2]+b[3])) + ((b[4]+b[5]) + (b[6]+b[7]));
    dot += __shfl_xor_sync(0xffffffffu, dot, 1);     // full 64-term dot
    if (REN) {
        mm = fmaxf(mm, __shfl_xor_sync(0xffffffffu, mm, 1));  // uniform max of published u
        C += __logf(mm);
        return dot * g * __fdividef(1.0f, mm);
    }
    return dot * g;
}

__global__ __launch_bounds__(256, 1)
void crf_kernel(const float* __restrict__ enc,     // [B,S,L]
                const float* __restrict__ trans,   // [L,L]
                const int*   __restrict__ lens,    // [B]
                const int*   __restrict__ tags,    // [B,S]
                float*       __restrict__ out)     // [2*B]
{
    __shared__ float spbuf[2][2][LL];   // [half][parity][state]
    __shared__ float sP[LL], sQ[LL];
    __shared__ float sC[2];
    __shared__ float sred[8];
    const int tid = threadIdx.x;

    if (blockIdx.x < BB) {
        const int b = blockIdx.x;
        const int h  = tid >> 7;        // 0 = forward, 1 = backward
        const int lt = tid & 127;
        const int x  = lt >> 1;
        const int s  = lt & 1;
        const int barid = 1 + h;

        const int len = lens[b];
        const int m = (len + 1) >> 1;   // meeting point: need p_{m-1}, q_{m-1}
        const float* encb = enc + (size_t)b * SS * LL;

        float C = 0.0f;
        float W[32];

        if (h == 0) {
            // ---------- forward: u_t = (E^T u_{t-1}) * f_t, t = 1..m-1 ----------
            #pragma unroll
            for (int i = 0; i < 32; i++)
                W[i] = __expf(trans[(32 * s + i) * LL + x]);   // E[i][x]
            float u = __expf(trans[TSTART * LL + x] + encb[x]); // p_0

            const int N = m - 1;                                // steps
            float fq[4];
            #pragma unroll
            for (int k0 = 0; k0 < 4; k0++)
                fq[k0] = __expf(encb[min(1 + k0, N) * LL + x]);

            int k = 1;
            for (; k + 3 <= N; k += 4) {
                float er[4];
                #pragma unroll
                for (int k0 = 0; k0 < 4; k0++)
                    er[k0] = encb[min(k + 4 + k0, N) * LL + x];
                u = stepf<false>(u, fq[0], spbuf[0][(k    ) & 1], W, x, s, barid, C);
                u = stepf<false>(u, fq[1], spbuf[0][(k + 1) & 1], W, x, s, barid, C);
                u = stepf<false>(u, fq[2], spbuf[0][(k + 2) & 1], W, x, s, barid, C);
                u = stepf<true >(u, fq[3], spbuf[0][(k + 3) & 1], W, x, s, barid, C);
                #pragma unroll
                for (int k0 = 0; k0 < 4; k0++) fq[k0] = __expf(er[k0]);
            }
            #pragma unroll
            for (int k0 = 0; k0 < 3; k0++) {
                if (k + k0 <= N) {
                    if (((k + k0) & 3) == 0)
                        u = stepf<true >(u, fq[k0], spbuf[0][(k + k0) & 1], W, x, s, barid, C);
                    else
                        u = stepf<false>(u, fq[k0], spbuf[0][(k + k0) & 1], W, x, s, barid, C);
                }
            }
            if (s == 0) sP[x] = u;      // p_{m-1} (up to exp(C))
            if (lt == 0) sC[0] = C;
        } else {
            // ---------- backward: u_t = f_t * q_t ; q_{t-1} = E u_t ----------
            #pragma unroll
            for (int i = 0; i < 32; i++)
                W[i] = __expf(trans[x * LL + 32 * s + i]);     // E[x][k]
            float u = __expf(trans[x * LL + TSTOP] + encb[(size_t)(len - 1) * LL + x]); // f_{len-1}*eStop

            const int Nb = len - m;       // total steps; last one has g = 1
            const int Ng = Nb - 1;        // steps consuming f_{len-1-k}
            float fq[4];
            #pragma unroll
            for (int k0 = 0; k0 < 4; k0++)
                fq[k0] = __expf(encb[(size_t)(len - 1 - min(1 + k0, Ng)) * LL + x]);

            int k = 1;
            for (; k + 3 <= Ng; k += 4) {
                float er[4];
                #pragma unroll
                for (int k0 = 0; k0 < 4; k0++)
                    er[k0] = encb[(size_t)(len - 1 - min(k + 4 + k0, Ng)) * LL + x];
                u = stepf<false>(u, fq[0], spbuf[1][(k    ) & 1], W, x, s, barid, C);
                u = stepf<false>(u, fq[1], spbuf[1][(k + 1) & 1], W, x, s, barid, C);
                u = stepf<false>(u, fq[2], spbuf[1][(k + 2) & 1], W, x, s, barid, C);
                u = stepf<true >(u, fq[3], spbuf[1][(k + 3) & 1], W, x, s, barid, C);
                #pragma unroll
                for (int k0 = 0; k0 < 4; k0++) fq[k0] = __expf(er[k0]);
            }
            #pragma unroll
            for (int k0 = 0; k0 < 3; k0++) {
                if (k + k0 <= Ng) {
                    if (((k + k0) & 3) == 0)
                        u = stepf<true >(u, fq[k0], spbuf[1][(k + k0) & 1], W, x, s, barid, C);
                    else
                        u = stepf<false>(u, fq[k0], spbuf[1][(k + k0) & 1], W, x, s, barid, C);
                }
            }
            // final step, g = 1: produces q_{m-1}
            float d = stepf<false>(u, 1.0f, spbuf[1][Nb & 1], W, x, s, barid, C);
            if (s == 0) sQ[x] = d;
            if (lt == 0) sC[1] = C;
        }

        __syncthreads();
        // unlabeled = C_f + C_b + log( sum_j p_{m-1}[j] * q_{m-1}[j] )
        if (tid < 32) {
            float v = sP[tid] * sQ[tid] + sP[tid + 32] * sQ[tid + 32];
            #pragma unroll
            for (int off = 16; off; off >>= 1)
                v += __shfl_xor_sync(0xffffffffu, v, off);
            if (tid == 0) out[b] = sC[0] + sC[1] + __logf(v);
        }
    } else {
        // ---------------- labeled path score ----------------
        const int b = blockIdx.x - BB;
        const int len = lens[b];
        const float* encb = enc + (size_t)b * SS * LL;
        const int* tg = tags + b * SS;

        float acc = 0.f;
        for (int t = 1 + tid; t < len; t += 256) {
            const int tt = tg[t];
            const int tp = tg[t - 1];
            acc += trans[tp * LL + tt] + encb[t * LL + tt];
        }
        #pragma unroll
        for (int off = 16; off; off >>= 1)
            acc += __shfl_xor_sync(0xffffffffu, acc, off);
        if ((tid & 31) == 0) sred[tid >> 5] = acc;
        __syncthreads();
        if (tid == 0) {
            float tot = 0.f;
            #pragma unroll
            for (int w = 0; w < 8; w++) tot += sred[w];
            const int t0 = tg[0];
            const float begin = trans[TSTART * LL + t0] + encb[t0];
            const float endsc = trans[tg[len - 1] * LL + TSTOP];
            out[BB + b] = tot + begin + endsc;
        }
    }
}

extern "C" void kernel_launch(void* const* d_in, const int* in_sizes, int n_in,
                              void* d_out, int out_size) {
    const float* enc   = (const float*)d_in[0];   // encoder_scores [32,512,64]
    const float* trans = (const float*)d_in[1];   // transition [64,64]
    const int*   lens  = (const int*)d_in[2];     // word_seq_lens [32]
    const int*   tags  = (const int*)d_in[3];     // tags [32,512]
    // d_in[4] = mask: unused (recomputed from lens)
    float* out = (float*)d_out;                   // [64] = unlabeled(32) ++ labeled(32)
    (void)in_sizes; (void)n_in; (void)out_size;

    crf_kernel<<<2 * BB, 256>>>(enc, trans, lens, tags, out);
}

// round 5
// speedup vs baseline: 1.7944x; 1.1795x over previous
#include <cuda_runtime.h>

#define BB 32
#define SS 512
#define LL 64
#define TSTART 61
#define TSTOP 62

// Cross-block handoff scratch (zero-initialized; flags restored to 0 every run).
__device__ float gP[BB][LL];
__device__ float gCf[BB];
__device__ int   gFlag[BB];

// One scan step for a 128-thread block. Thread (x = tid>>1, s = tid&1) owns output
// state x and the i-range [32s,32s+32) of the 64-term dot (weights in W[32]).
template<bool REN>
__device__ __forceinline__ float stepf(float u, float g, float* spb, const float* W,
                                       int x, int s, float& C) {
    if (s == 0) spb[x] = u;
    __syncthreads();
    const float4* sp4 = (const float4*)spb + 8 * s;
    float b[8], mm = 0.f;
    #pragma unroll
    for (int k = 0; k < 8; k++) {
        const float4 v = sp4[k];
        b[k] = fmaf(v.x, W[4*k+0], fmaf(v.y, W[4*k+1], fmaf(v.z, W[4*k+2], v.w * W[4*k+3])));
        if (REN) mm = fmaxf(mm, fmaxf(fmaxf(v.x, v.y), fmaxf(v.z, v.w)));
    }
    float dot = ((b[0]+b[1]) + (b[2]+b[3])) + ((b[4]+b[5]) + (b[6]+b[7]));
    dot += __shfl_xor_sync(0xffffffffu, dot, 1);          // full 64-term dot
    if (REN) {
        mm = fmaxf(mm, __shfl_xor_sync(0xffffffffu, mm, 1)); // uniform max of published u
        C += __logf(mm);
        return dot * g * __fdividef(1.0f, mm);
    }
    return dot * g;
}

__global__ __launch_bounds__(128, 1)
void crf_kernel(const float* __restrict__ enc,     // [B,S,L]
                const float* __restrict__ trans,   // [L,L]
                const int*   __restrict__ lens,    // [B]
                const int*   __restrict__ tags,    // [B,S]
                float*       __restrict__ out)     // [2*B]
{
    __shared__ float spbuf[2][LL];
    __shared__ float sQ[LL];
    __shared__ float sred[4];
    const int tid = threadIdx.x;
    const int x = tid >> 1;
    const int s = tid & 1;

    if (blockIdx.x < BB) {
        // ================= forward scan: p_0 .. p_{m-1} =================
        const int b = blockIdx.x;
        const int len = lens[b];
        const int m = (len + 1) >> 1;
        const float* encb = enc + (size_t)b * SS * LL;

        float W[32];
        #pragma unroll
        for (int i = 0; i < 32; i++)
            W[i] = __expf(trans[(32 * s + i) * LL + x]);    // E[i][x]
        float u = __expf(trans[TSTART * LL + x] + encb[x]); // p_0
        float C = 0.0f;

        const int N = m - 1;
        float fq[4];
        #pragma unroll
        for (int k0 = 0; k0 < 4; k0++)
            fq[k0] = __expf(encb[min(1 + k0, N) * LL + x]);

        int k = 1;
        for (; k + 3 <= N; k += 4) {
            float er[4];
            #pragma unroll
            for (int k0 = 0; k0 < 4; k0++)
                er[k0] = encb[min(k + 4 + k0, N) * LL + x];
            u = stepf<false>(u, fq[0], spbuf[(k    ) & 1], W, x, s, C);
            u = stepf<false>(u, fq[1], spbuf[(k + 1) & 1], W, x, s, C);
            u = stepf<false>(u, fq[2], spbuf[(k + 2) & 1], W, x, s, C);
            u = stepf<true >(u, fq[3], spbuf[(k + 3) & 1], W, x, s, C);
            #pragma unroll
            for (int k0 = 0; k0 < 4; k0++) fq[k0] = __expf(er[k0]);
        }
        #pragma unroll
        for (int k0 = 0; k0 < 3; k0++) {
            if (k + k0 <= N) {
                if (((k + k0) & 3) == 0)
                    u = stepf<true >(u, fq[k0], spbuf[(k + k0) & 1], W, x, s, C);
                else
                    u = stepf<false>(u, fq[k0], spbuf[(k + k0) & 1], W, x, s, C);
            }
        }

        // publish p_{m-1}, C_f; release flag
        if (s == 0) gP[b][x] = u;
        __threadfence();
        __syncthreads();
        if (tid == 0) {
            gCf[b] = C;
            __threadfence();
            atomicExch(&gFlag[b], 1);
        }
    } else if (blockIdx.x < 2 * BB) {
        // ================= backward scan: q_{len-1} .. q_{m-1} =================
        const int b = blockIdx.x - BB;
        const int len = lens[b];
        const int m = (len + 1) >> 1;
        const float* encb = enc + (size_t)b * SS * LL;

        float W[32];
        #pragma unroll
        for (int i = 0; i < 32; i++)
            W[i] = __expf(trans[x * LL + 32 * s + i]);      // E[x][k]
        float u = __expf(trans[x * LL + TSTOP] + encb[(size_t)(len - 1) * LL + x]);
        float C = 0.0f;

        const int Nb = len - m;       // total steps; last one has g = 1
        const int Ng = Nb - 1;
        float fq[4];
        #pragma unroll
        for (int k0 = 0; k0 < 4; k0++)
            fq[k0] = __expf(encb[(size_t)(len - 1 - min(1 + k0, Ng)) * LL + x]);

        int k = 1;
        for (; k + 3 <= Ng; k += 4) {
            float er[4];
            #pragma unroll
            for (int k0 = 0; k0 < 4; k0++)
                er[k0] = encb[(size_t)(len - 1 - min(k + 4 + k0, Ng)) * LL + x];
            u = stepf<false>(u, fq[0], spbuf[(k    ) & 1], W, x, s, C);
            u = stepf<false>(u, fq[1], spbuf[(k + 1) & 1], W, x, s, C);
            u = stepf<false>(u, fq[2], spbuf[(k + 2) & 1], W, x, s, C);
            u = stepf<true >(u, fq[3], spbuf[(k + 3) & 1], W, x, s, C);
            #pragma unroll
            for (int k0 = 0; k0 < 4; k0++) fq[k0] = __expf(er[k0]);
        }
        #pragma unroll
        for (int k0 = 0; k0 < 3; k0++) {
            if (k + k0 <= Ng) {
                if (((k + k0) & 3) == 0)
                    u = stepf<true >(u, fq[k0], spbuf[(k + k0) & 1], W, x, s, C);
                else
                    u = stepf<false>(u, fq[k0], spbuf[(k + k0) & 1], W, x, s, C);
            }
        }
        // final step, g = 1: produces q_{m-1}
        float d = stepf<false>(u, 1.0f, spbuf[Nb & 1], W, x, s, C);
        if (s == 0) sQ[x] = d;
        __syncthreads();

        // acquire forward result
        if (tid == 0) {
            while (atomicAdd(&gFlag[b], 0) == 0) { }
        }
        __syncthreads();
        __threadfence();

        // combine: out[b] = C_f + C_b + log( sum_j p[j]*q[j] )
        if (tid < 32) {
            float v = gP[b][tid] * sQ[tid] + gP[b][tid + 32] * sQ[tid + 32];
            #pragma unroll
            for (int off = 16; off; off >>= 1)
                v += __shfl_xor_sync(0xffffffffu, v, off);
            if (tid == 0) out[b] = gCf[b] + C + __logf(v);
        }
        __syncthreads();
        if (tid == 0) atomicExch(&gFlag[b], 0);   // restore for next replay
    } else {
        // ================= labeled path score =================
        const int b = blockIdx.x - 2 * BB;
        const int len = lens[b];
        const float* encb = enc + (size_t)b * SS * LL;
        const int* tg = tags + b * SS;

        float acc = 0.f;
        for (int t = 1 + tid; t < len; t += 128) {
            const int tt = tg[t];
            const int tp = tg[t - 1];
            acc += trans[tp * LL + tt] + encb[t * LL + tt];
        }
        #pragma unroll
        for (int off = 16; off; off >>= 1)
            acc += __shfl_xor_sync(0xffffffffu, acc, off);
        if ((tid & 31) == 0) sred[tid >> 5] = acc;
        __syncthreads();
        if (tid == 0) {
            const int t0 = tg[0];
            const float begin = trans[TSTART * LL + t0] + encb[t0];
            const float endsc = trans[tg[len - 1] * LL + TSTOP];
            out[BB + b] = ((sred[0] + sred[1]) + (sred[2] + sred[3])) + begin + endsc;
        }
    }
}

extern "C" void kernel_launch(void* const* d_in, const int* in_sizes, int n_in,
                              void* d_out, int out_size) {
    const float* enc   = (const float*)d_in[0];   // encoder_scores [32,512,64]
    const float* trans = (const float*)d_in[1];   // transition [64,64]
    const int*   lens  = (const int*)d_in[2];     // word_seq_lens [32]
    const int*   tags  = (const int*)d_in[3];     // tags [32,512]
    // d_in[4] = mask: unused (recomputed from lens)
    float* out = (float*)d_out;                   // [64] = unlabeled(32) ++ labeled(32)
    (void)in_sizes; (void)n_in; (void)out_size;

    crf_kernel<<<3 * BB, 128>>>(enc, trans, lens, tags, out);
}

// round 6
// speedup vs baseline: 2.2383x; 1.2474x over previous
#include <cuda_runtime.h>

#define BB 32
#define SS 512
#define LL 64
#define TSTART 61
#define TSTOP 62

typedef unsigned long long ull;

// Cross-block handoff scratch (zero-initialized; flags restored to 0 every run).
__device__ float gP[BB][LL];
__device__ float gCf[BB];
__device__ int   gFlag[BB];

__device__ __forceinline__ ull fma2(ull a, ull b, ull c) {
    ull d; asm("fma.rn.f32x2 %0, %1, %2, %3;" : "=l"(d) : "l"(a), "l"(b), "l"(c)); return d;
}
__device__ __forceinline__ ull mul2(ull a, ull b) {
    ull d; asm("mul.rn.f32x2 %0, %1, %2;" : "=l"(d) : "l"(a), "l"(b)); return d;
}
__device__ __forceinline__ ull add2(ull a, ull b) {
    ull d; asm("add.rn.f32x2 %0, %1, %2;" : "=l"(d) : "l"(a), "l"(b)); return d;
}
__device__ __forceinline__ ull pack2(float lo, float hi) {
    ull d; asm("mov.b64 %0, {%1, %2};" : "=l"(d) : "r"(__float_as_uint(lo)), "r"(__float_as_uint(hi))); return d;
}
__device__ __forceinline__ float2 unpack2(ull v) {
    unsigned lo, hi; asm("mov.b64 {%0, %1}, %2;" : "=r"(lo), "=r"(hi) : "l"(v));
    return make_float2(__uint_as_float(lo), __uint_as_float(hi));
}

// One scan step, 64 threads / 2 warps. Thread x owns state x and computes the
// full 64-term dot with packed f32x2 FMAs. Wp[m] = (w[2m], w[2m+1]).
// Renorm (REN): uniform scale by p_prev[0] (state 0 is always finite).
template<bool REN>
__device__ __forceinline__ float step64(float u, float f, float* spb,
                                        const ull* Wp, int x, float& C) {
    spb[x] = u;
    __syncthreads();
    const ulonglong2* sp2 = (const ulonglong2*)spb;   // 16 x 16B, broadcast reads
    ull acc[8];
    #pragma unroll
    for (int k = 0; k < 8; k++) {
        const ulonglong2 a = sp2[k];
        const ulonglong2 b = sp2[k + 8];
        ull t = fma2(a.y, Wp[2*k + 1], mul2(a.x, Wp[2*k]));
        t = fma2(b.x, Wp[2*k + 16], t);
        acc[k] = fma2(b.y, Wp[2*k + 17], t);
    }
    ull t0 = add2(add2(acc[0], acc[1]), add2(acc[2], acc[3]));
    ull t1 = add2(add2(acc[4], acc[5]), add2(acc[6], acc[7]));
    const float2 tf = unpack2(add2(t0, t1));
    const float dot = tf.x + tf.y;
    if (REN) {
        const float v0 = spb[0];               // uniform, finite
        C += __logf(v0);
        return dot * f * __fdividef(1.0f, v0);
    }
    return dot * f;
}

__global__ __launch_bounds__(64, 1)
void crf_kernel(const float* __restrict__ enc,     // [B,S,L]
                const float* __restrict__ trans,   // [L,L]
                const int*   __restrict__ lens,    // [B]
                const int*   __restrict__ tags,    // [B,S]
                float*       __restrict__ out)     // [2*B]
{
    __shared__ float spbuf[2][LL];
    __shared__ float sQ[LL];
    __shared__ float sred[2];
    const int tid = threadIdx.x;
    const int x = tid;

    if (blockIdx.x < BB) {
        // ================= forward scan: p_0 .. p_{m-1} =================
        const int b = blockIdx.x;
        const int len = lens[b];
        const int m = (len + 1) >> 1;
        const float* encb = enc + (size_t)b * SS * LL;

        ull Wp[32];                        // Wp[m] = (E[2m][x], E[2m+1][x])
        #pragma unroll
        for (int i = 0; i < 32; i++)
            Wp[i] = pack2(__expf(trans[(2*i) * LL + x]),
                          __expf(trans[(2*i + 1) * LL + x]));
        float u = __expf(trans[TSTART * LL + x] + encb[x]);   // p_0
        float C = 0.0f;

        const int N = m - 1;
        float fq[4];
        #pragma unroll
        for (int k0 = 0; k0 < 4; k0++)
            fq[k0] = __expf(encb[min(1 + k0, N) * LL + x]);

        int k = 1;
        for (; k + 3 <= N; k += 4) {
            float er[4];
            #pragma unroll
            for (int k0 = 0; k0 < 4; k0++)
                er[k0] = encb[min(k + 4 + k0, N) * LL + x];
            u = step64<false>(u, fq[0], spbuf[(k    ) & 1], Wp, x, C);
            u = step64<false>(u, fq[1], spbuf[(k + 1) & 1], Wp, x, C);
            u = step64<false>(u, fq[2], spbuf[(k + 2) & 1], Wp, x, C);
            u = step64<true >(u, fq[3], spbuf[(k + 3) & 1], Wp, x, C);
            #pragma unroll
            for (int k0 = 0; k0 < 4; k0++) fq[k0] = __expf(er[k0]);
        }
        #pragma unroll
        for (int k0 = 0; k0 < 3; k0++) {
            if (k + k0 <= N) {
                if (((k + k0) & 3) == 0)
                    u = step64<true >(u, fq[k0], spbuf[(k + k0) & 1], Wp, x, C);
                else
                    u = step64<false>(u, fq[k0], spbuf[(k + k0) & 1], Wp, x, C);
            }
        }

        // publish p_{m-1}, C_f; release flag
        gP[b][x] = u;
        __threadfence();
        __syncthreads();
        if (tid == 0) {
            gCf[b] = C;
            __threadfence();
            atomicExch(&gFlag[b], 1);
        }
    } else if (blockIdx.x < 2 * BB) {
        // ================= backward scan: q_{len-1} .. q_{m-1} =================
        const int b = blockIdx.x - BB;
        const int len = lens[b];
        const int m = (len + 1) >> 1;
        const float* encb = enc + (size_t)b * SS * LL;

        ull Wp[32];                        // Wp[m] = (E[x][2m], E[x][2m+1])
        #pragma unroll
        for (int i = 0; i < 32; i++)
            Wp[i] = pack2(__expf(trans[x * LL + 2*i]),
                          __expf(trans[x * LL + 2*i + 1]));
        float u = __expf(trans[x * LL + TSTOP] + encb[(size_t)(len - 1) * LL + x]);
        float C = 0.0f;

        const int Nb = len - m;       // total steps; last one has g = 1
        const int Ng = Nb - 1;
        float fq[4];
        #pragma unroll
        for (int k0 = 0; k0 < 4; k0++)
            fq[k0] = __expf(encb[(size_t)(len - 1 - min(1 + k0, Ng)) * LL + x]);

        int k = 1;
        for (; k + 3 <= Ng; k += 4) {
            float er[4];
            #pragma unroll
            for (int k0 = 0; k0 < 4; k0++)
                er[k0] = encb[(size_t)(len - 1 - min(k + 4 + k0, Ng)) * LL + x];
            u = step64<false>(u, fq[0], spbuf[(k    ) & 1], Wp, x, C);
            u = step64<false>(u, fq[1], spbuf[(k + 1) & 1], Wp, x, C);
            u = step64<false>(u, fq[2], spbuf[(k + 2) & 1], Wp, x, C);
            u = step64<true >(u, fq[3], spbuf[(k + 3) & 1], Wp, x, C);
            #pragma unroll
            for (int k0 = 0; k0 < 4; k0++) fq[k0] = __expf(er[k0]);
        }
        #pragma unroll
        for (int k0 = 0; k0 < 3; k0++) {
            if (k + k0 <= Ng) {
                if (((k + k0) & 3) == 0)
                    u = step64<true >(u, fq[k0], spbuf[(k + k0) & 1], Wp, x, C);
                else
                    u = step64<false>(u, fq[k0], spbuf[(k + k0) & 1], Wp, x, C);
            }
        }
        // final step, g = 1: produces q_{m-1}
        const float d = step64<false>(u, 1.0f, spbuf[Nb & 1], Wp, x, C);
        sQ[x] = d;
        __syncthreads();

        // acquire forward result
        if (tid == 0) {
            while (atomicAdd(&gFlag[b], 0) == 0) { }
        }
        __syncthreads();
        __threadfence();

        // combine: out[b] = C_f + C_b + log( sum_j p[j]*q[j] )
        if (tid < 32) {
            float v = gP[b][tid] * sQ[tid] + gP[b][tid + 32] * sQ[tid + 32];
            #pragma unroll
            for (int off = 16; off; off >>= 1)
                v += __shfl_xor_sync(0xffffffffu, v, off);
            if (tid == 0) out[b] = gCf[b] + C + __logf(v);
        }
        __syncthreads();
        if (tid == 0) atomicExch(&gFlag[b], 0);   // restore for next replay
    } else {
        // ================= labeled path score =================
        const int b = blockIdx.x - 2 * BB;
        const int len = lens[b];
        const float* encb = enc + (size_t)b * SS * LL;
        const int* tg = tags + b * SS;

        float acc = 0.f;
        for (int t = 1 + tid; t < len; t += 64) {
            const int tt = tg[t];
            const int tp = tg[t - 1];
            acc += trans[tp * LL + tt] + encb[t * LL + tt];
        }
        #pragma unroll
        for (int off = 16; off; off >>= 1)
            acc += __shfl_xor_sync(0xffffffffu, acc, off);
        if ((tid & 31) == 0) sred[tid >> 5] = acc;
        __syncthreads();
        if (tid == 0) {
            const int t0 = tg[0];
            const float begin = trans[TSTART * LL + t0] + encb[t0];
            const float endsc = trans[tg[len - 1] * LL + TSTOP];
            out[BB + b] = sred[0] + sred[1] + begin + endsc;
        }
    }
}

extern "C" void kernel_launch(void* const* d_in, const int* in_sizes, int n_in,
                              void* d_out, int out_size) {
    const float* enc   = (const float*)d_in[0];   // encoder_scores [32,512,64]
    const float* trans = (const float*)d_in[1];   // transition [64,64]
    const int*   lens  = (const int*)d_in[2];     // word_seq_lens [32]
    const int*   tags  = (const int*)d_in[3];     // tags [32,512]
    // d_in[4] = mask: unused (recomputed from lens)
    float* out = (float*)d_out;                   // [64] = unlabeled(32) ++ labeled(32)
    (void)in_sizes; (void)n_in; (void)out_size;

    crf_kernel<<<3 * BB, 64>>>(enc, trans, lens, tags, out);
}

// round 8
// speedup vs baseline: 2.2692x; 1.0138x over previous
#include <cuda_runtime.h>

#define BB 32
#define SS 512
#define LL 64
#define TSTART 61
#define TSTOP 62

typedef unsigned long long ull;

// Cross-block handoff scratch (zero-initialized; flags restored to 0 every run).
__device__ float gP[BB][LL];
__device__ float gCf[BB];
__device__ int   gFlag[BB];

__device__ __forceinline__ ull fma2(ull a, ull b, ull c) {
    ull d; asm("fma.rn.f32x2 %0, %1, %2, %3;" : "=l"(d) : "l"(a), "l"(b), "l"(c)); return d;
}
__device__ __forceinline__ ull mul2(ull a, ull b) {
    ull d; asm("mul.rn.f32x2 %0, %1, %2;" : "=l"(d) : "l"(a), "l"(b)); return d;
}
__device__ __forceinline__ ull add2(ull a, ull b) {
    ull d; asm("add.rn.f32x2 %0, %1, %2;" : "=l"(d) : "l"(a), "l"(b)); return d;
}
__device__ __forceinline__ ull pack2(float lo, float hi) {
    ull d; asm("mov.b64 %0, {%1, %2};" : "=l"(d) : "r"(__float_as_uint(lo)), "r"(__float_as_uint(hi))); return d;
}
__device__ __forceinline__ float2 unpack2(ull v) {
    unsigned lo, hi; asm("mov.b64 {%0, %1}, %2;" : "=r"(lo), "=r"(hi) : "l"(v));
    return make_float2(__uint_as_float(lo), __uint_as_float(hi));
}

// One scan step, 64 threads / 2 warps. Thread x owns state x and computes the
// full 64-term dot with packed f32x2 FMAs. Wp[m] = (w[2m], w[2m+1]).
// Renorm (REN): uniform scale by p_prev[0] (state 0 is always finite).
template<bool REN>
__device__ __forceinline__ float step64(float u, float f, float* spb,
                                        const ull* Wp, int x, float& C) {
    spb[x] = u;
    __syncthreads();
    const ulonglong2* sp2 = (const ulonglong2*)spb;   // 16 x 16B, broadcast reads
    ull acc[8];
    #pragma unroll
    for (int k = 0; k < 8; k++) {
        const ulonglong2 a = sp2[k];
        const ulonglong2 b = sp2[k + 8];
        ull t = fma2(a.y, Wp[2*k + 1], mul2(a.x, Wp[2*k]));
        t = fma2(b.x, Wp[2*k + 16], t);
        acc[k] = fma2(b.y, Wp[2*k + 17], t);
    }
    ull t0 = add2(add2(acc[0], acc[1]), add2(acc[2], acc[3]));
    ull t1 = add2(add2(acc[4], acc[5]), add2(acc[6], acc[7]));
    const float2 tf = unpack2(add2(t0, t1));
    const float dot = tf.x + tf.y;
    if (REN) {
        const float v0 = spb[0];               // uniform, finite
        C += __logf(v0);
        return dot * f * __fdividef(1.0f, v0);
    }
    return dot * f;
}

__global__ __launch_bounds__(64, 1)
void crf_kernel(const float* __restrict__ enc,     // [B,S,L]
                const float* __restrict__ trans,   // [L,L]
                const int*   __restrict__ lens,    // [B]
                const int*   __restrict__ tags,    // [B,S]
                float*       __restrict__ out)     // [2*B]
{
    __shared__ float spbuf[2][LL];
    __shared__ float sQ[LL];
    __shared__ float sred[2];
    const int tid = threadIdx.x;
    const int x = tid;

    if (blockIdx.x < BB) {
        // ================= forward scan: p_0 .. p_{m-1} =================
        const int b = blockIdx.x;
        const int len = lens[b];
        const int m = (len + 1) >> 1;
        const float* encb = enc + (size_t)b * SS * LL;

        ull Wp[32];                        // Wp[m] = (E[2m][x], E[2m+1][x])
        #pragma unroll
        for (int i = 0; i < 32; i++)
            Wp[i] = pack2(__expf(trans[(2*i) * LL + x]),
                          __expf(trans[(2*i + 1) * LL + x]));
        float u = __expf(trans[TSTART * LL + x] + encb[x]);   // p_0
        float C = 0.0f;

        const int N = m - 1;
        float fq[4];
        #pragma unroll
        for (int k0 = 0; k0 < 4; k0++)
            fq[k0] = __expf(encb[min(1 + k0, N) * LL + x]);

        int k = 1;
        for (; k + 3 <= N; k += 4) {
            float er[4];
            #pragma unroll
            for (int k0 = 0; k0 < 4; k0++)
                er[k0] = encb[min(k + 4 + k0, N) * LL + x];
            u = step64<false>(u, fq[0], spbuf[(k    ) & 1], Wp, x, C);
            u = step64<false>(u, fq[1], spbuf[(k + 1) & 1], Wp, x, C);
            u = step64<false>(u, fq[2], spbuf[(k + 2) & 1], Wp, x, C);
            u = step64<true >(u, fq[3], spbuf[(k + 3) & 1], Wp, x, C);
            #pragma unroll
            for (int k0 = 0; k0 < 4; k0++) fq[k0] = __expf(er[k0]);
        }
        #pragma unroll
        for (int k0 = 0; k0 < 3; k0++) {
            if (k + k0 <= N) {
                if (((k + k0) & 3) == 0)
                    u = step64<true >(u, fq[k0], spbuf[(k + k0) & 1], Wp, x, C);
                else
                    u = step64<false>(u, fq[k0], spbuf[(k + k0) & 1], Wp, x, C);
            }
        }

        // publish p_{m-1}, C_f; release flag
        gP[b][x] = u;
        __threadfence();
        __syncthreads();
        if (tid == 0) {
            gCf[b] = C;
            __threadfence();
            atomicExch(&gFlag[b], 1);
        }
    } else if (blockIdx.x < 2 * BB) {
        // ================= backward scan: q_{len-1} .. q_{m-1} =================
        const int b = blockIdx.x - BB;
        const int len = lens[b];
        const int m = (len + 1) >> 1;
        const float* encb = enc + (size_t)b * SS * LL;

        ull Wp[32];                        // Wp[m] = (E[x][2m], E[x][2m+1])
        #pragma unroll
        for (int i = 0; i < 32; i++)
            Wp[i] = pack2(__expf(trans[x * LL + 2*i]),
                          __expf(trans[x * LL + 2*i + 1]));
        float u = __expf(trans[x * LL + TSTOP] + encb[(size_t)(len - 1) * LL + x]);
        float C = 0.0f;

        const int Nb = len - m;       // total steps; last one has g = 1
        const int Ng = Nb - 1;
        float fq[4];
        #pragma unroll
        for (int k0 = 0; k0 < 4; k0++)
            fq[k0] = __expf(encb[(size_t)(len - 1 - min(1 + k0, Ng)) * LL + x]);

        int k = 1;
        for (; k + 3 <= Ng; k += 4) {
            float er[4];
            #pragma unroll
            for (int k0 = 0; k0 < 4; k0++)
                er[k0] = encb[(size_t)(len - 1 - min(k + 4 + k0, Ng)) * LL + x];
            u = step64<false>(u, fq[0], spbuf[(k    ) & 1], Wp, x, C);
            u = step64<false>(u, fq[1], spbuf[(k + 1) & 1], Wp, x, C);
            u = step64<false>(u, fq[2], spbuf[(k + 2) & 1], Wp, x, C);
            u = step64<true >(u, fq[3], spbuf[(k + 3) & 1], Wp, x, C);
            #pragma unroll
            for (int k0 = 0; k0 < 4; k0++) fq[k0] = __expf(er[k0]);
        }
        #pragma unroll
        for (int k0 = 0; k0 < 3; k0++) {
            if (k + k0 <= Ng) {
                if (((k + k0) & 3) == 0)
                    u = step64<true >(u, fq[k0], spbuf[(k + k0) & 1], Wp, x, C);
                else
                    u = step64<false>(u, fq[k0], spbuf[(k + k0) & 1], Wp, x, C);
            }
        }
        // final step, g = 1: produces q_{m-1}
        const float d = step64<false>(u, 1.0f, spbuf[Nb & 1], Wp, x, C);
        sQ[x] = d;
        __syncthreads();

        // acquire forward result
        if (tid == 0) {
            while (atomicAdd(&gFlag[b], 0) == 0) { }
        }
        __syncthreads();
        __threadfence();

        // combine: out[b] = C_f + C_b + log( sum_j p[j]*q[j] )
        if (tid < 32) {
            float v = gP[b][tid] * sQ[tid] + gP[b][tid + 32] * sQ[tid + 32];
            #pragma unroll
            for (int off = 16; off; off >>= 1)
                v += __shfl_xor_sync(0xffffffffu, v, off);
            if (tid == 0) out[b] = gCf[b] + C + __logf(v);
        }
        __syncthreads();
        if (tid == 0) atomicExch(&gFlag[b], 0);   // restore for next replay
    } else {
        // ================= labeled path score =================
        const int b = blockIdx.x - 2 * BB;
        const int len = lens[b];
        const float* encb = enc + (size_t)b * SS * LL;
        const int* tg = tags + b * SS;

        float acc = 0.f;
        for (int t = 1 + tid; t < len; t += 64) {
            const int tt = tg[t];
            const int tp = tg[t - 1];
            acc += trans[tp * LL + tt] + encb[t * LL + tt];
        }
        #pragma unroll
        for (int off = 16; off; off >>= 1)
            acc += __shfl_xor_sync(0xffffffffu, acc, off);
        if ((tid & 31) == 0) sred[tid >> 5] = acc;
        __syncthreads();
        if (tid == 0) {
            const int t0 = tg[0];
            const float begin = trans[TSTART * LL + t0] + encb[t0];
            const float endsc = trans[tg[len - 1] * LL + TSTOP];
            out[BB + b] = sred[0] + sred[1] + begin + endsc;
        }
    }
}

extern "C" void kernel_launch(void* const* d_in, const int* in_sizes, int n_in,
                              void* d_out, int out_size) {
    const float* enc   = (const float*)d_in[0];   // encoder_scores [32,512,64]
    const float* trans = (const float*)d_in[1];   // transition [64,64]
    const int*   lens  = (const int*)d_in[2];     // word_seq_lens [32]
    const int*   tags  = (const int*)d_in[3];     // tags [32,512]
    // d_in[4] = mask: unused (recomputed from lens)
    float* out = (float*)d_out;                   // [64] = unlabeled(32) ++ labeled(32)
    (void)in_sizes; (void)n_in; (void)out_size;

    crf_kernel<<<3 * BB, 64>>>(enc, trans, lens, tags, out);
}